// round 2
// baseline (speedup 1.0000x reference)
#include <cuda_runtime.h>
#include <cstdint>

// out[e] = sum_d |x[r[e],d] - x[c[e],d]| * w[d] + b[0]
// N_NODES=100000, N_EDGES=600000, D=128
//
// JAX default config disables x64: the "int64" index arrays are actually
// int32 on disk. Read as int32; clamp defensively so a wrong dtype guess
// shows up as rel_err, not an illegal access.
//
// One warp per edge: lane i handles dims [4i,4i+4) via float4 -> each
// gathered 512B row is 4 perfectly-coalesced 128B sectors. Node table
// (51.2MB) is L2-resident; w (512B) and b are L1-resident.

#define D_FEAT 128

__global__ __launch_bounds__(256, 8)
void edge_abs_dot_kernel(const float* __restrict__ x,
                         const int* __restrict__ r_idx,
                         const int* __restrict__ c_idx,
                         const float* __restrict__ w,
                         const float* __restrict__ b,
                         float* __restrict__ out,
                         int n_edges,
                         int n_nodes)
{
    const int warp_id = (blockIdx.x * blockDim.x + threadIdx.x) >> 5;
    const int lane    = threadIdx.x & 31;
    if (warp_id >= n_edges) return;

    // Broadcast index loads (single sector each, warp-uniform)
    int ri = __ldg(r_idx + warp_id);
    int ci = __ldg(c_idx + warp_id);
    // Defensive clamp: guarantees in-bounds even if dtype guess is wrong.
    ri = min(max(ri, 0), n_nodes - 1);
    ci = min(max(ci, 0), n_nodes - 1);

    const float4* ra = reinterpret_cast<const float4*>(x + (size_t)ri * D_FEAT);
    const float4* ca = reinterpret_cast<const float4*>(x + (size_t)ci * D_FEAT);
    const float4* wa = reinterpret_cast<const float4*>(w);

    const float4 av = __ldg(ra + lane);
    const float4 cv = __ldg(ca + lane);
    const float4 wv = __ldg(wa + lane);

    float s = fabsf(av.x - cv.x) * wv.x;
    s = fmaf(fabsf(av.y - cv.y), wv.y, s);
    s = fmaf(fabsf(av.z - cv.z), wv.z, s);
    s = fmaf(fabsf(av.w - cv.w), wv.w, s);

    // Warp reduction
    s += __shfl_down_sync(0xffffffffu, s, 16);
    s += __shfl_down_sync(0xffffffffu, s, 8);
    s += __shfl_down_sync(0xffffffffu, s, 4);
    s += __shfl_down_sync(0xffffffffu, s, 2);
    s += __shfl_down_sync(0xffffffffu, s, 1);

    if (lane == 0)
        out[warp_id] = s + __ldg(b);
}

extern "C" void kernel_launch(void* const* d_in, const int* in_sizes, int n_in,
                              void* d_out, int out_size)
{
    const float* x     = (const float*)d_in[0];   // [N_NODES, 128] fp32
    const int*   r_idx = (const int*)d_in[1];     // [E] int32 (jax x64 off)
    const int*   c_idx = (const int*)d_in[2];     // [E] int32
    const float* w     = (const float*)d_in[3];   // [128, 1] fp32
    const float* b     = (const float*)d_in[4];   // [1] fp32
    float*       out   = (float*)d_out;           // [E] fp32

    const int n_edges = in_sizes[1];              // 600000
    const int n_nodes = in_sizes[0] / D_FEAT;     // 100000

    const int threads = 256;                      // 8 warps = 8 edges/block
    const int warps_per_block = threads / 32;
    const int blocks = (n_edges + warps_per_block - 1) / warps_per_block;

    edge_abs_dot_kernel<<<blocks, threads>>>(x, r_idx, c_idx, w, b, out,
                                             n_edges, n_nodes);
}

// round 3
// speedup vs baseline: 1.6212x; 1.6212x over previous
#include <cuda_runtime.h>
#include <cstdint>

// out[e] = sum_d |x[r[e],d] - x[c[e],d]| * w[d] + b[0]
// N_NODES=100000, N_EDGES=600000, D=128 (indices are int32: jax x64 disabled)
//
// Warp processes 32 edges:
//  - w (float4 per lane) and b hoisted to registers (saves 4 L1 wavefronts/edge)
//  - indices loaded coalesced once per warp, broadcast via shfl (saves 2/edge)
//  - butterfly reduction; edge j's sum parked in lane j; one coalesced store
//  - unroll 4 -> 8 independent LDG.128 gathers in flight per warp

#define D_FEAT 128

__global__ __launch_bounds__(256, 8)
void edge_abs_dot_kernel(const float* __restrict__ x,
                         const int* __restrict__ r_idx,
                         const int* __restrict__ c_idx,
                         const float* __restrict__ w,
                         const float* __restrict__ b,
                         float* __restrict__ out,
                         int n_edges,
                         int n_nodes)
{
    const int lane  = threadIdx.x & 31;
    const int gwarp = (blockIdx.x * blockDim.x + threadIdx.x) >> 5;
    const int base  = gwarp << 5;               // 32 edges per warp
    if (base >= n_edges) return;

    // Per-lane slice of w (dims [4*lane, 4*lane+4)) lives in registers.
    const float4 wv = __ldg(reinterpret_cast<const float4*>(w) + lane);
    const float  bb = __ldg(b);

    // Coalesced index loads: lane holds edge (base+lane)'s endpoints.
    const int  eidx  = base + lane;
    const bool valid = (eidx < n_edges);
    int ridx = valid ? __ldg(r_idx + eidx) : 0;
    int cidx = valid ? __ldg(c_idx + eidx) : 0;
    // Defensive clamp (in-bounds guaranteed even on bad data).
    ridx = min(max(ridx, 0), n_nodes - 1);
    cidx = min(max(cidx, 0), n_nodes - 1);

    float res = 0.0f;

    #pragma unroll 4
    for (int j = 0; j < 32; ++j) {
        const int ri = __shfl_sync(0xffffffffu, ridx, j);
        const int ci = __shfl_sync(0xffffffffu, cidx, j);

        const float4 av = __ldg(reinterpret_cast<const float4*>(
                                    x + (size_t)ri * D_FEAT) + lane);
        const float4 cv = __ldg(reinterpret_cast<const float4*>(
                                    x + (size_t)ci * D_FEAT) + lane);

        float s = fabsf(av.x - cv.x) * wv.x;
        s = fmaf(fabsf(av.y - cv.y), wv.y, s);
        s = fmaf(fabsf(av.z - cv.z), wv.z, s);
        s = fmaf(fabsf(av.w - cv.w), wv.w, s);

        // Butterfly reduction: every lane ends with the full sum.
        s += __shfl_xor_sync(0xffffffffu, s, 16);
        s += __shfl_xor_sync(0xffffffffu, s, 8);
        s += __shfl_xor_sync(0xffffffffu, s, 4);
        s += __shfl_xor_sync(0xffffffffu, s, 2);
        s += __shfl_xor_sync(0xffffffffu, s, 1);

        if (lane == j) res = s;
    }

    if (valid)
        out[eidx] = res + bb;   // coalesced 32-lane store
}

extern "C" void kernel_launch(void* const* d_in, const int* in_sizes, int n_in,
                              void* d_out, int out_size)
{
    const float* x     = (const float*)d_in[0];   // [N_NODES, 128] fp32
    const int*   r_idx = (const int*)d_in[1];     // [E] int32
    const int*   c_idx = (const int*)d_in[2];     // [E] int32
    const float* w     = (const float*)d_in[3];   // [128, 1] fp32
    const float* b     = (const float*)d_in[4];   // [1] fp32
    float*       out   = (float*)d_out;           // [E] fp32

    const int n_edges = in_sizes[1];              // 600000
    const int n_nodes = in_sizes[0] / D_FEAT;     // 100000

    const int threads = 256;                      // 8 warps/block
    const int edges_per_block = (threads / 32) * 32;   // 256 edges
    const int blocks = (n_edges + edges_per_block - 1) / edges_per_block;

    edge_abs_dot_kernel<<<blocks, threads>>>(x, r_idx, c_idx, w, b, out,
                                             n_edges, n_nodes);
}

// round 4
// speedup vs baseline: 1.6239x; 1.0016x over previous
#include <cuda_runtime.h>
#include <cstdint>

// out[e] = sum_d |x[r[e],d] - x[c[e],d]| * w[d] + b[0]
// N_NODES=100000, N_EDGES=600000, D=128 (indices int32: jax x64 disabled)
//
// Warp handles 32 edges. Gathers issued as LDG.64 (float2) so each warp
// load instruction spans 256B = 2 L1 lines (vs 4 for LDG.128), cutting
// within-instruction L1tex replay cycles (~2.07 cyc/extra line measured on
// B300). Lane i covers dims {2i,2i+1} and {64+2i,64+2i+1}.
// w slices + b live in registers; indices loaded coalesced and broadcast
// via shfl; butterfly reduction parks edge j's result in lane j; one
// coalesced store per warp.

#define D_FEAT 128

__global__ __launch_bounds__(256, 8)
void edge_abs_dot_kernel(const float* __restrict__ x,
                         const int* __restrict__ r_idx,
                         const int* __restrict__ c_idx,
                         const float* __restrict__ w,
                         const float* __restrict__ b,
                         float* __restrict__ out,
                         int n_edges,
                         int n_nodes)
{
    const int lane  = threadIdx.x & 31;
    const int gwarp = (blockIdx.x * blockDim.x + threadIdx.x) >> 5;
    const int base  = gwarp << 5;               // 32 edges per warp
    if (base >= n_edges) return;

    // Per-lane w slices in registers: dims {2lane,2lane+1}, {64+2lane,...}
    const float2* w2 = reinterpret_cast<const float2*>(w);
    const float2 wv0 = __ldg(w2 + lane);
    const float2 wv1 = __ldg(w2 + 32 + lane);
    const float  bb  = __ldg(b);

    // Coalesced index loads: lane holds edge (base+lane)'s endpoints.
    const int  eidx  = base + lane;
    const bool valid = (eidx < n_edges);
    int ridx = valid ? __ldg(r_idx + eidx) : 0;
    int cidx = valid ? __ldg(c_idx + eidx) : 0;
    ridx = min(max(ridx, 0), n_nodes - 1);
    cidx = min(max(cidx, 0), n_nodes - 1);

    float res = 0.0f;

    #pragma unroll 4
    for (int j = 0; j < 32; ++j) {
        const int ri = __shfl_sync(0xffffffffu, ridx, j);
        const int ci = __shfl_sync(0xffffffffu, cidx, j);

        const float2* ra = reinterpret_cast<const float2*>(
                               x + (size_t)ri * D_FEAT);
        const float2* ca = reinterpret_cast<const float2*>(
                               x + (size_t)ci * D_FEAT);

        // Two 256B (2-line) gathers per row
        const float2 a0 = __ldg(ra + lane);
        const float2 a1 = __ldg(ra + 32 + lane);
        const float2 c0 = __ldg(ca + lane);
        const float2 c1 = __ldg(ca + 32 + lane);

        float s = fabsf(a0.x - c0.x) * wv0.x;
        s = fmaf(fabsf(a0.y - c0.y), wv0.y, s);
        s = fmaf(fabsf(a1.x - c1.x), wv1.x, s);
        s = fmaf(fabsf(a1.y - c1.y), wv1.y, s);

        // Butterfly reduction: every lane ends with the full sum.
        s += __shfl_xor_sync(0xffffffffu, s, 16);
        s += __shfl_xor_sync(0xffffffffu, s, 8);
        s += __shfl_xor_sync(0xffffffffu, s, 4);
        s += __shfl_xor_sync(0xffffffffu, s, 2);
        s += __shfl_xor_sync(0xffffffffu, s, 1);

        if (lane == j) res = s;
    }

    if (valid)
        out[eidx] = res + bb;   // coalesced 32-lane store
}

extern "C" void kernel_launch(void* const* d_in, const int* in_sizes, int n_in,
                              void* d_out, int out_size)
{
    const float* x     = (const float*)d_in[0];   // [N_NODES, 128] fp32
    const int*   r_idx = (const int*)d_in[1];     // [E] int32
    const int*   c_idx = (const int*)d_in[2];     // [E] int32
    const float* w     = (const float*)d_in[3];   // [128, 1] fp32
    const float* b     = (const float*)d_in[4];   // [1] fp32
    float*       out   = (float*)d_out;           // [E] fp32

    const int n_edges = in_sizes[1];              // 600000
    const int n_nodes = in_sizes[0] / D_FEAT;     // 100000

    const int threads = 256;                      // 8 warps/block
    const int edges_per_block = (threads / 32) * 32;   // 256 edges
    const int blocks = (n_edges + edges_per_block - 1) / edges_per_block;

    edge_abs_dot_kernel<<<blocks, threads>>>(x, r_idx, c_idx, w, b, out,
                                             n_edges, n_nodes);
}

// round 5
// speedup vs baseline: 1.7013x; 1.0477x over previous
#include <cuda_runtime.h>
#include <cstdint>

// out[e] = sum_d |x[r[e],d] - x[c[e],d]| * w[d] + b[0]
// N_NODES=100000, N_EDGES=600000, D=128 (indices int32: jax x64 disabled)
//
// 8 lanes per edge, 4 edges per warp-iteration, 32 edges per warp:
//  - every LDG.128 instruction = 4 rows x one full 128B line (min wavefronts,
//    100% useful bytes per wavefront)
//  - 3-step xor butterfly reduces 4 edges at once (0.75 shfl/edge)
//  - 2 index shfl per 4 edges (0.5/edge); total shuffles 7 -> 1.25 per edge
//  - w slices + b in registers; coalesced index preload; permuted single-line store

#define D_FEAT 128

__global__ __launch_bounds__(256)
void edge_abs_dot_kernel(const float* __restrict__ x,
                         const int* __restrict__ r_idx,
                         const int* __restrict__ c_idx,
                         const float* __restrict__ w,
                         const float* __restrict__ b,
                         float* __restrict__ out,
                         int n_edges,
                         int n_nodes)
{
    const int lane  = threadIdx.x & 31;
    const int g     = lane >> 3;        // group 0..3 (one edge each)
    const int t     = lane & 7;         // position within group
    const int gwarp = (blockIdx.x * blockDim.x + threadIdx.x) >> 5;
    const int base  = gwarp << 5;       // 32 edges per warp
    if (base >= n_edges) return;

    // Per-lane w slice: lane covers dims {4*(t+8k) .. +4} for k=0..3
    const float4* w4 = reinterpret_cast<const float4*>(w);
    float4 wv[4];
    #pragma unroll
    for (int k = 0; k < 4; ++k) wv[k] = __ldg(w4 + t + 8 * k);
    const float bb = __ldg(b);

    // Coalesced index preload: lane holds edge (base+lane)'s endpoints.
    const int eload = min(base + lane, n_edges - 1);
    int ridx = __ldg(r_idx + eload);
    int cidx = __ldg(c_idx + eload);
    ridx = min(max(ridx, 0), n_nodes - 1);
    cidx = min(max(cidx, 0), n_nodes - 1);

    float res = 0.0f;

    #pragma unroll 2
    for (int j = 0; j < 8; ++j) {
        // group g works on edge base + 4j + g
        const int src = 4 * j + g;
        const int ri = __shfl_sync(0xffffffffu, ridx, src);
        const int ci = __shfl_sync(0xffffffffu, cidx, src);

        const float4* ra = reinterpret_cast<const float4*>(
                               x + (size_t)ri * D_FEAT);
        const float4* ca = reinterpret_cast<const float4*>(
                               x + (size_t)ci * D_FEAT);

        float4 av[4], cv[4];
        #pragma unroll
        for (int k = 0; k < 4; ++k) {
            av[k] = __ldg(ra + t + 8 * k);
            cv[k] = __ldg(ca + t + 8 * k);
        }

        float s = 0.0f;
        #pragma unroll
        for (int k = 0; k < 4; ++k) {
            s = fmaf(fabsf(av[k].x - cv[k].x), wv[k].x, s);
            s = fmaf(fabsf(av[k].y - cv[k].y), wv[k].y, s);
            s = fmaf(fabsf(av[k].z - cv[k].z), wv[k].z, s);
            s = fmaf(fabsf(av[k].w - cv[k].w), wv[k].w, s);
        }

        // Reduce within each 8-lane group (4 edges reduced simultaneously)
        s += __shfl_xor_sync(0xffffffffu, s, 4);
        s += __shfl_xor_sync(0xffffffffu, s, 2);
        s += __shfl_xor_sync(0xffffffffu, s, 1);

        if (t == j) res = s;     // lane 8g+j holds edge base+4j+g
    }

    // Lane L (g=L>>3, j=L&7) stores edge base + 4*(L&7) + (L>>3).
    // All 32 targets lie in one 128B line -> single store wavefront.
    const int estore = base + 4 * t + g;
    if (estore < n_edges)
        out[estore] = res + bb;
}

extern "C" void kernel_launch(void* const* d_in, const int* in_sizes, int n_in,
                              void* d_out, int out_size)
{
    const float* x     = (const float*)d_in[0];   // [N_NODES, 128] fp32
    const int*   r_idx = (const int*)d_in[1];     // [E] int32
    const int*   c_idx = (const int*)d_in[2];     // [E] int32
    const float* w     = (const float*)d_in[3];   // [128, 1] fp32
    const float* b     = (const float*)d_in[4];   // [1] fp32
    float*       out   = (float*)d_out;           // [E] fp32

    const int n_edges = in_sizes[1];              // 600000
    const int n_nodes = in_sizes[0] / D_FEAT;     // 100000

    const int threads = 256;                      // 8 warps/block
    const int edges_per_block = (threads / 32) * 32;   // 256 edges
    const int blocks = (n_edges + edges_per_block - 1) / edges_per_block;

    edge_abs_dot_kernel<<<blocks, threads>>>(x, r_idx, c_idx, w, b, out,
                                             n_edges, n_nodes);
}

// round 6
// speedup vs baseline: 1.7129x; 1.0069x over previous
#include <cuda_runtime.h>
#include <cstdint>

// out[e] = sum_d |x[r[e],d] - x[c[e],d]| * w[d] + b[0]
// N_NODES=100000, N_EDGES=600000, D=128 (indices int32: jax x64 disabled)
//
// 16 lanes per edge, 2 edges per warp-iteration, 32 edges per warp.
// Register-lean on purpose (R5 postmortem: 60 regs -> 45% occ -> latency
// exposed). Only 4 float4 loads live per iteration, w slice = 2 float4.
// Every LDG.128 instruction covers 4 full 128B lines (2 rows x 2 lines).
// 4-step butterfly reduces 2 edges simultaneously; 1 index shfl per edge.
// Latency hidden by occupancy (target 6-7 blocks/SM) instead of unroll.

#define D_FEAT 128

__global__ __launch_bounds__(256)
void edge_abs_dot_kernel(const float* __restrict__ x,
                         const int* __restrict__ r_idx,
                         const int* __restrict__ c_idx,
                         const float* __restrict__ w,
                         const float* __restrict__ b,
                         float* __restrict__ out,
                         int n_edges,
                         int n_nodes)
{
    const int lane  = threadIdx.x & 31;
    const int g     = lane >> 4;        // group 0..1 (one edge each)
    const int t     = lane & 15;        // position within group
    const int gwarp = (blockIdx.x * blockDim.x + threadIdx.x) >> 5;
    const int base  = gwarp << 5;       // 32 edges per warp
    if (base >= n_edges) return;

    // Per-lane w slice: dims {4t..4t+3} and {64+4t..64+4t+3}
    const float4* w4 = reinterpret_cast<const float4*>(w);
    const float4 wv0 = __ldg(w4 + t);
    const float4 wv1 = __ldg(w4 + 16 + t);
    const float  bb  = __ldg(b);

    // Coalesced index preload: lane holds edge (base+lane)'s endpoints.
    const int eload = min(base + lane, n_edges - 1);
    int ridx = __ldg(r_idx + eload);
    int cidx = __ldg(c_idx + eload);
    ridx = min(max(ridx, 0), n_nodes - 1);
    cidx = min(max(cidx, 0), n_nodes - 1);

    float res = 0.0f;

    #pragma unroll 1
    for (int j = 0; j < 16; ++j) {
        // group g works on edge base + 2j + g
        const int src = 2 * j + g;
        const int ri = __shfl_sync(0xffffffffu, ridx, src);
        const int ci = __shfl_sync(0xffffffffu, cidx, src);

        const float4* ra = reinterpret_cast<const float4*>(
                               x + (size_t)ri * D_FEAT);
        const float4* ca = reinterpret_cast<const float4*>(
                               x + (size_t)ci * D_FEAT);

        const float4 a0 = __ldg(ra + t);
        const float4 a1 = __ldg(ra + 16 + t);
        const float4 c0 = __ldg(ca + t);
        const float4 c1 = __ldg(ca + 16 + t);

        float s;
        s = fabsf(a0.x - c0.x) * wv0.x;
        s = fmaf(fabsf(a0.y - c0.y), wv0.y, s);
        s = fmaf(fabsf(a0.z - c0.z), wv0.z, s);
        s = fmaf(fabsf(a0.w - c0.w), wv0.w, s);
        s = fmaf(fabsf(a1.x - c1.x), wv1.x, s);
        s = fmaf(fabsf(a1.y - c1.y), wv1.y, s);
        s = fmaf(fabsf(a1.z - c1.z), wv1.z, s);
        s = fmaf(fabsf(a1.w - c1.w), wv1.w, s);

        // Reduce within each 16-lane group (2 edges simultaneously)
        s += __shfl_xor_sync(0xffffffffu, s, 8);
        s += __shfl_xor_sync(0xffffffffu, s, 4);
        s += __shfl_xor_sync(0xffffffffu, s, 2);
        s += __shfl_xor_sync(0xffffffffu, s, 1);

        if (t == j) res = s;    // lane 16g+j holds edge base+2j+g
    }

    // Lane L (g=L>>4, t=L&15) stores edge base + 2t + g.
    // All 32 targets lie in one 128B line -> single store wavefront.
    const int estore = base + 2 * t + g;
    if (estore < n_edges)
        out[estore] = res + bb;
}

extern "C" void kernel_launch(void* const* d_in, const int* in_sizes, int n_in,
                              void* d_out, int out_size)
{
    const float* x     = (const float*)d_in[0];   // [N_NODES, 128] fp32
    const int*   r_idx = (const int*)d_in[1];     // [E] int32
    const int*   c_idx = (const int*)d_in[2];     // [E] int32
    const float* w     = (const float*)d_in[3];   // [128, 1] fp32
    const float* b     = (const float*)d_in[4];   // [1] fp32
    float*       out   = (float*)d_out;           // [E] fp32

    const int n_edges = in_sizes[1];              // 600000
    const int n_nodes = in_sizes[0] / D_FEAT;     // 100000

    const int threads = 256;                      // 8 warps/block
    const int edges_per_block = (threads / 32) * 32;   // 256 edges
    const int blocks = (n_edges + edges_per_block - 1) / edges_per_block;

    edge_abs_dot_kernel<<<blocks, threads>>>(x, r_idx, c_idx, w, b, out,
                                             n_edges, n_nodes);
}

// round 7
// speedup vs baseline: 1.8339x; 1.0706x over previous
#include <cuda_runtime.h>
#include <cuda_fp16.h>
#include <cstdint>

// out[e] = sum_d |x[r[e],d] - x[c[e],d]| * w[d] + b[0]
// N_NODES=100000, N_EDGES=600000, D=128 (indices int32: jax x64 disabled)
//
// R3-R6 postmortem: runtime is pinned at ~37us by the L1tex gather line
// rate (~2.07 cyc per 128B line, 8 lines/edge in fp32) regardless of load
// width / lanes-per-edge / occupancy. Only reducing lines/edge helps.
//
// Plan: prologue kernel converts the node table fp32 -> fp16 into a
// __device__ scratch (25.6MB, L2-resident). Main kernel gathers 256B fp16
// rows = 2 lines/row -> 4 lines/edge (2x less L1tex work). Math stays in
// fp32 after exact fp16->fp32 converts; expected rel_err ~3e-4 << 1e-3.

#define D_FEAT   128
#define MAX_NODES 100000

// fp16 node table: 100000 rows x 128 halves = 16 uint4 per row.
__device__ uint4 g_xh[MAX_NODES * (D_FEAT / 8)];

__global__ __launch_bounds__(256)
void convert_fp16_kernel(const float* __restrict__ x, int n_vec)
{
    const int i = blockIdx.x * blockDim.x + threadIdx.x;
    if (i >= n_vec) return;

    const float4* xf = reinterpret_cast<const float4*>(x);
    const float4 f0 = __ldg(xf + 2 * i);
    const float4 f1 = __ldg(xf + 2 * i + 1);

    const __half2 h0 = __floats2half2_rn(f0.x, f0.y);
    const __half2 h1 = __floats2half2_rn(f0.z, f0.w);
    const __half2 h2 = __floats2half2_rn(f1.x, f1.y);
    const __half2 h3 = __floats2half2_rn(f1.z, f1.w);

    uint4 o;
    o.x = *reinterpret_cast<const unsigned int*>(&h0);
    o.y = *reinterpret_cast<const unsigned int*>(&h1);
    o.z = *reinterpret_cast<const unsigned int*>(&h2);
    o.w = *reinterpret_cast<const unsigned int*>(&h3);
    g_xh[i] = o;
}

__device__ __forceinline__ float2 h2f(unsigned int u)
{
    return __half22float2(*reinterpret_cast<const __half2*>(&u));
}

__global__ __launch_bounds__(256)
void edge_abs_dot_kernel(const int* __restrict__ r_idx,
                         const int* __restrict__ c_idx,
                         const float* __restrict__ w,
                         const float* __restrict__ b,
                         float* __restrict__ out,
                         int n_edges,
                         int n_nodes)
{
    const int lane  = threadIdx.x & 31;
    const int g     = lane >> 4;        // group 0..1 (one edge each)
    const int t     = lane & 15;        // position within group
    const int gwarp = (blockIdx.x * blockDim.x + threadIdx.x) >> 5;
    const int base  = gwarp << 5;       // 32 edges per warp
    if (base >= n_edges) return;

    // Per-lane w slice: dims {8t .. 8t+7} in fp32
    const float4* w4 = reinterpret_cast<const float4*>(w);
    const float4 wv0 = __ldg(w4 + 2 * t);
    const float4 wv1 = __ldg(w4 + 2 * t + 1);
    const float  bb  = __ldg(b);

    // Coalesced index preload: lane holds edge (base+lane)'s endpoints.
    const int eload = min(base + lane, n_edges - 1);
    int ridx = __ldg(r_idx + eload);
    int cidx = __ldg(c_idx + eload);
    ridx = min(max(ridx, 0), n_nodes - 1);
    cidx = min(max(cidx, 0), n_nodes - 1);

    float res = 0.0f;

    #pragma unroll 1
    for (int j = 0; j < 16; ++j) {
        // group g works on edge base + 2j + g
        const int src = 2 * j + g;
        const int ri = __shfl_sync(0xffffffffu, ridx, src);
        const int ci = __shfl_sync(0xffffffffu, cidx, src);

        // One LDG.128 per endpoint row: 16 lanes x 16B = whole 256B row.
        const uint4 ua = g_xh[(size_t)ri * 16 + t];
        const uint4 uc = g_xh[(size_t)ci * 16 + t];

        const float2 a0 = h2f(ua.x), a1 = h2f(ua.y),
                     a2 = h2f(ua.z), a3 = h2f(ua.w);
        const float2 c0 = h2f(uc.x), c1 = h2f(uc.y),
                     c2 = h2f(uc.z), c3 = h2f(uc.w);

        float s;
        s = fabsf(a0.x - c0.x) * wv0.x;
        s = fmaf(fabsf(a0.y - c0.y), wv0.y, s);
        s = fmaf(fabsf(a1.x - c1.x), wv0.z, s);
        s = fmaf(fabsf(a1.y - c1.y), wv0.w, s);
        s = fmaf(fabsf(a2.x - c2.x), wv1.x, s);
        s = fmaf(fabsf(a2.y - c2.y), wv1.y, s);
        s = fmaf(fabsf(a3.x - c3.x), wv1.z, s);
        s = fmaf(fabsf(a3.y - c3.y), wv1.w, s);

        // Reduce within each 16-lane group (2 edges simultaneously)
        s += __shfl_xor_sync(0xffffffffu, s, 8);
        s += __shfl_xor_sync(0xffffffffu, s, 4);
        s += __shfl_xor_sync(0xffffffffu, s, 2);
        s += __shfl_xor_sync(0xffffffffu, s, 1);

        if (t == j) res = s;    // lane 16g+j holds edge base+2j+g
    }

    // Lane L (g=L>>4, t=L&15) stores edge base + 2t + g.
    // All 32 targets lie in one 128B line -> single store wavefront.
    const int estore = base + 2 * t + g;
    if (estore < n_edges)
        out[estore] = res + bb;
}

extern "C" void kernel_launch(void* const* d_in, const int* in_sizes, int n_in,
                              void* d_out, int out_size)
{
    const float* x     = (const float*)d_in[0];   // [N_NODES, 128] fp32
    const int*   r_idx = (const int*)d_in[1];     // [E] int32
    const int*   c_idx = (const int*)d_in[2];     // [E] int32
    const float* w     = (const float*)d_in[3];   // [128, 1] fp32
    const float* b     = (const float*)d_in[4];   // [1] fp32
    float*       out   = (float*)d_out;           // [E] fp32

    const int n_edges = in_sizes[1];              // 600000
    int n_nodes = in_sizes[0] / D_FEAT;           // 100000
    if (n_nodes > MAX_NODES) n_nodes = MAX_NODES;

    // 1) fp32 -> fp16 node table (each thread emits one uint4 = 8 halves)
    const int n_vec = n_nodes * (D_FEAT / 8);     // 1.6M
    convert_fp16_kernel<<<(n_vec + 255) / 256, 256>>>(x, n_vec);

    // 2) edge gather + abs-diff dot
    const int threads = 256;                      // 8 warps/block
    const int edges_per_block = (threads / 32) * 32;   // 256 edges
    const int blocks = (n_edges + edges_per_block - 1) / edges_per_block;
    edge_abs_dot_kernel<<<blocks, threads>>>(r_idx, c_idx, w, b, out,
                                             n_edges, n_nodes);
}

// round 8
// speedup vs baseline: 2.0336x; 1.1089x over previous
#include <cuda_runtime.h>
#include <cuda_fp16.h>
#include <cstdint>

// out[e] = sum_d |x[r[e],d] - x[c[e],d]| * w[d] + b[0]
// N_NODES=100000, N_EDGES=600000, D=128 (indices int32: jax x64 disabled)
//
// Two kernels: (1) fp32->fp16 node-table conversion into __device__ scratch
// (25.6MB, L2-resident; BW-bound ~8us), (2) edge gather at 4 L1 lines/edge.
// R8: half2 math (HSUB2 + HABS2-on-ALU + HFMA2 4-term slot accumulation,
// fp32 cross-lane reduce) cuts FMA-pipe ops 24->10 per lane-iter, plus a
// one-iteration load prefetch to overlap gather latency with math.

#define D_FEAT    128
#define MAX_NODES 100000

// fp16 node table: 100000 rows x 128 halves = 16 uint4 per row (256B rows).
__device__ __align__(256) uint4 g_xh[MAX_NODES * (D_FEAT / 8)];

__global__ __launch_bounds__(256)
void convert_fp16_kernel(const float* __restrict__ x, int n_vec)
{
    const int i = blockIdx.x * blockDim.x + threadIdx.x;
    if (i >= n_vec) return;

    const float4* xf = reinterpret_cast<const float4*>(x);
    const float4 f0 = __ldg(xf + 2 * i);
    const float4 f1 = __ldg(xf + 2 * i + 1);

    const __half2 h0 = __floats2half2_rn(f0.x, f0.y);
    const __half2 h1 = __floats2half2_rn(f0.z, f0.w);
    const __half2 h2 = __floats2half2_rn(f1.x, f1.y);
    const __half2 h3 = __floats2half2_rn(f1.z, f1.w);

    uint4 o;
    o.x = *reinterpret_cast<const unsigned int*>(&h0);
    o.y = *reinterpret_cast<const unsigned int*>(&h1);
    o.z = *reinterpret_cast<const unsigned int*>(&h2);
    o.w = *reinterpret_cast<const unsigned int*>(&h3);
    g_xh[i] = o;
}

__device__ __forceinline__ __half2 u2h(unsigned int u)
{
    return *reinterpret_cast<const __half2*>(&u);
}

__global__ __launch_bounds__(256)
void edge_abs_dot_kernel(const int* __restrict__ r_idx,
                         const int* __restrict__ c_idx,
                         const float* __restrict__ w,
                         const float* __restrict__ b,
                         float* __restrict__ out,
                         int n_edges,
                         int n_nodes)
{
    const int lane  = threadIdx.x & 31;
    const int g     = lane >> 4;        // group 0..1 (one edge each)
    const int t     = lane & 15;        // position within group
    const int gwarp = (blockIdx.x * blockDim.x + threadIdx.x) >> 5;
    const int base  = gwarp << 5;       // 32 edges per warp
    if (base >= n_edges) return;

    // Per-lane w slice (dims 8t..8t+7) converted once to half2.
    const float4* w4 = reinterpret_cast<const float4*>(w);
    const float4 wv0 = __ldg(w4 + 2 * t);
    const float4 wv1 = __ldg(w4 + 2 * t + 1);
    const __half2 wh0 = __floats2half2_rn(wv0.x, wv0.y);
    const __half2 wh1 = __floats2half2_rn(wv0.z, wv0.w);
    const __half2 wh2 = __floats2half2_rn(wv1.x, wv1.y);
    const __half2 wh3 = __floats2half2_rn(wv1.z, wv1.w);
    const float   bb  = __ldg(b);

    // Coalesced index preload: lane holds edge (base+lane)'s endpoints.
    const int eload = min(base + lane, n_edges - 1);
    int ridx = __ldg(r_idx + eload);
    int cidx = __ldg(c_idx + eload);
    ridx = min(max(ridx, 0), n_nodes - 1);
    cidx = min(max(cidx, 0), n_nodes - 1);

    // Software pipeline: prefetch iteration 0's rows.
    int ri = __shfl_sync(0xffffffffu, ridx, g);
    int ci = __shfl_sync(0xffffffffu, cidx, g);
    uint4 ua = g_xh[(size_t)ri * 16 + t];
    uint4 uc = g_xh[(size_t)ci * 16 + t];

    float res = 0.0f;

    #pragma unroll 4
    for (int j = 0; j < 16; ++j) {
        const uint4 a = ua;
        const uint4 c = uc;
        if (j < 15) {
            const int src = 2 * (j + 1) + g;
            ri = __shfl_sync(0xffffffffu, ridx, src);
            ci = __shfl_sync(0xffffffffu, cidx, src);
            ua = g_xh[(size_t)ri * 16 + t];
            uc = g_xh[(size_t)ci * 16 + t];
        }

        // |a - c| in half2 (HABS2 = LOP3 on ALU pipe), 4-term HFMA2 slots.
        const __half2 d0 = __habs2(__hsub2(u2h(a.x), u2h(c.x)));
        const __half2 d1 = __habs2(__hsub2(u2h(a.y), u2h(c.y)));
        const __half2 d2 = __habs2(__hsub2(u2h(a.z), u2h(c.z)));
        const __half2 d3 = __habs2(__hsub2(u2h(a.w), u2h(c.w)));

        __half2 p = __hmul2(d0, wh0);
        p = __hfma2(d1, wh1, p);
        p = __hfma2(d2, wh2, p);
        p = __hfma2(d3, wh3, p);

        const float2 pf = __half22float2(p);
        float s = pf.x + pf.y;

        // Reduce within each 16-lane group (2 edges simultaneously), fp32.
        s += __shfl_xor_sync(0xffffffffu, s, 8);
        s += __shfl_xor_sync(0xffffffffu, s, 4);
        s += __shfl_xor_sync(0xffffffffu, s, 2);
        s += __shfl_xor_sync(0xffffffffu, s, 1);

        if (t == j) res = s;    // lane 16g+j holds edge base+2j+g
    }

    // Lane L (g=L>>4, t=L&15) stores edge base + 2t + g.
    // All 32 targets lie in one 128B line -> single store wavefront.
    const int estore = base + 2 * t + g;
    if (estore < n_edges)
        out[estore] = res + bb;
}

extern "C" void kernel_launch(void* const* d_in, const int* in_sizes, int n_in,
                              void* d_out, int out_size)
{
    const float* x     = (const float*)d_in[0];   // [N_NODES, 128] fp32
    const int*   r_idx = (const int*)d_in[1];     // [E] int32
    const int*   c_idx = (const int*)d_in[2];     // [E] int32
    const float* w     = (const float*)d_in[3];   // [128, 1] fp32
    const float* b     = (const float*)d_in[4];   // [1] fp32
    float*       out   = (float*)d_out;           // [E] fp32

    const int n_edges = in_sizes[1];              // 600000
    int n_nodes = in_sizes[0] / D_FEAT;           // 100000
    if (n_nodes > MAX_NODES) n_nodes = MAX_NODES;

    // 1) fp32 -> fp16 node table (each thread emits one uint4 = 8 halves)
    const int n_vec = n_nodes * (D_FEAT / 8);     // 1.6M
    convert_fp16_kernel<<<(n_vec + 255) / 256, 256>>>(x, n_vec);

    // 2) edge gather + abs-diff dot
    const int threads = 256;                      // 8 warps/block
    const int edges_per_block = (threads / 32) * 32;   // 256 edges
    const int blocks = (n_edges + edges_per_block - 1) / edges_per_block;
    edge_abs_dot_kernel<<<blocks, threads>>>(r_idx, c_idx, w, b, out,
                                             n_edges, n_nodes);
}

// round 9
// speedup vs baseline: 2.0482x; 1.0072x over previous
#include <cuda_runtime.h>
#include <cuda_fp16.h>
#include <cstdint>

// out[e] = sum_d |x[r[e],d] - x[c[e],d]| * w[d] + b[0]
// N_NODES=100000, N_EDGES=600000, D=128 (indices int32: jax x64 disabled)
//
// Kernel 1: fp32->fp16 node table into __device__ scratch (25.6MB,
//           L2-resident; traffic-bound ~5us).
// Kernel 2: edge gather at 4 L1 lines/edge, half2 math, fp32 reduce.
// R9: depth-2 software pipeline (prefetch j+2 while computing j) to cover
// L2-hit latency (234cyc) that a 1-deep prefetch couldn't; index offsets
// pre-scaled before shfl to kill per-iter IMAD address math.

#define D_FEAT    128
#define MAX_NODES 100000

// fp16 node table: 100000 rows x 128 halves = 16 uint4 per row (256B rows).
__device__ __align__(256) uint4 g_xh[MAX_NODES * (D_FEAT / 8)];

__global__ __launch_bounds__(256)
void convert_fp16_kernel(const float* __restrict__ x, int n_vec)
{
    const int i = blockIdx.x * blockDim.x + threadIdx.x;
    if (i >= n_vec) return;

    const float4* xf = reinterpret_cast<const float4*>(x);
    const float4 f0 = __ldg(xf + 2 * i);
    const float4 f1 = __ldg(xf + 2 * i + 1);

    const __half2 h0 = __floats2half2_rn(f0.x, f0.y);
    const __half2 h1 = __floats2half2_rn(f0.z, f0.w);
    const __half2 h2 = __floats2half2_rn(f1.x, f1.y);
    const __half2 h3 = __floats2half2_rn(f1.z, f1.w);

    uint4 o;
    o.x = *reinterpret_cast<const unsigned int*>(&h0);
    o.y = *reinterpret_cast<const unsigned int*>(&h1);
    o.z = *reinterpret_cast<const unsigned int*>(&h2);
    o.w = *reinterpret_cast<const unsigned int*>(&h3);
    g_xh[i] = o;
}

__device__ __forceinline__ __half2 u2h(unsigned int u)
{
    return *reinterpret_cast<const __half2*>(&u);
}

__global__ __launch_bounds__(256)
void edge_abs_dot_kernel(const int* __restrict__ r_idx,
                         const int* __restrict__ c_idx,
                         const float* __restrict__ w,
                         const float* __restrict__ b,
                         float* __restrict__ out,
                         int n_edges,
                         int n_nodes)
{
    const int lane  = threadIdx.x & 31;
    const int g     = lane >> 4;        // group 0..1 (one edge each)
    const int t     = lane & 15;        // position within group
    const int gwarp = (blockIdx.x * blockDim.x + threadIdx.x) >> 5;
    const int base  = gwarp << 5;       // 32 edges per warp
    if (base >= n_edges) return;

    // Per-lane w slice (dims 8t..8t+7) converted once to half2.
    const float4* w4 = reinterpret_cast<const float4*>(w);
    const float4 wv0 = __ldg(w4 + 2 * t);
    const float4 wv1 = __ldg(w4 + 2 * t + 1);
    const __half2 wh0 = __floats2half2_rn(wv0.x, wv0.y);
    const __half2 wh1 = __floats2half2_rn(wv0.z, wv0.w);
    const __half2 wh2 = __floats2half2_rn(wv1.x, wv1.y);
    const __half2 wh3 = __floats2half2_rn(wv1.z, wv1.w);
    const float   bb  = __ldg(b);

    // Coalesced index preload; pre-scale to uint4-element offsets so the
    // loop does no multiplies (shfl carries the scaled offset).
    const int eload = min(base + lane, n_edges - 1);
    int ridx = __ldg(r_idx + eload);
    int cidx = __ldg(c_idx + eload);
    ridx = min(max(ridx, 0), n_nodes - 1);
    cidx = min(max(cidx, 0), n_nodes - 1);
    const int roff = ridx << 4;         // row start in uint4 units
    const int coff = cidx << 4;

    // Depth-2 software pipeline: iterations j and j+1 in flight.
    uint4 a_cur, c_cur, a_nxt, c_nxt;
    {
        const int s0 = g;                       // j=0: edge base+g
        const int s1 = 2 + g;                   // j=1: edge base+2+g
        const int ro0 = __shfl_sync(0xffffffffu, roff, s0);
        const int co0 = __shfl_sync(0xffffffffu, coff, s0);
        const int ro1 = __shfl_sync(0xffffffffu, roff, s1);
        const int co1 = __shfl_sync(0xffffffffu, coff, s1);
        a_cur = g_xh[ro0 + t];
        c_cur = g_xh[co0 + t];
        a_nxt = g_xh[ro1 + t];
        c_nxt = g_xh[co1 + t];
    }

    float res = 0.0f;

    #pragma unroll 4
    for (int j = 0; j < 16; ++j) {
        const uint4 a = a_cur;
        const uint4 c = c_cur;
        a_cur = a_nxt;
        c_cur = c_nxt;
        if (j < 14) {
            const int src = 2 * (j + 2) + g;
            const int ro = __shfl_sync(0xffffffffu, roff, src);
            const int co = __shfl_sync(0xffffffffu, coff, src);
            a_nxt = g_xh[ro + t];
            c_nxt = g_xh[co + t];
        }

        // |a - c| in half2 (HABS2 on ALU pipe), 4-term HFMA2 accumulation.
        const __half2 d0 = __habs2(__hsub2(u2h(a.x), u2h(c.x)));
        const __half2 d1 = __habs2(__hsub2(u2h(a.y), u2h(c.y)));
        const __half2 d2 = __habs2(__hsub2(u2h(a.z), u2h(c.z)));
        const __half2 d3 = __habs2(__hsub2(u2h(a.w), u2h(c.w)));

        __half2 p = __hmul2(d0, wh0);
        p = __hfma2(d1, wh1, p);
        p = __hfma2(d2, wh2, p);
        p = __hfma2(d3, wh3, p);

        const float2 pf = __half22float2(p);
        float s = pf.x + pf.y;

        // Reduce within each 16-lane group (2 edges simultaneously), fp32.
        s += __shfl_xor_sync(0xffffffffu, s, 8);
        s += __shfl_xor_sync(0xffffffffu, s, 4);
        s += __shfl_xor_sync(0xffffffffu, s, 2);
        s += __shfl_xor_sync(0xffffffffu, s, 1);

        if (t == j) res = s;    // lane 16g+j holds edge base+2j+g
    }

    // Lane L (g=L>>4, t=L&15) stores edge base + 2t + g.
    // All 32 targets lie in one 128B line -> single store wavefront.
    const int estore = base + 2 * t + g;
    if (estore < n_edges)
        out[estore] = res + bb;
}

extern "C" void kernel_launch(void* const* d_in, const int* in_sizes, int n_in,
                              void* d_out, int out_size)
{
    const float* x     = (const float*)d_in[0];   // [N_NODES, 128] fp32
    const int*   r_idx = (const int*)d_in[1];     // [E] int32
    const int*   c_idx = (const int*)d_in[2];     // [E] int32
    const float* w     = (const float*)d_in[3];   // [128, 1] fp32
    const float* b     = (const float*)d_in[4];   // [1] fp32
    float*       out   = (float*)d_out;           // [E] fp32

    const int n_edges = in_sizes[1];              // 600000
    int n_nodes = in_sizes[0] / D_FEAT;           // 100000
    if (n_nodes > MAX_NODES) n_nodes = MAX_NODES;

    // 1) fp32 -> fp16 node table (each thread emits one uint4 = 8 halves)
    const int n_vec = n_nodes * (D_FEAT / 8);     // 1.6M
    convert_fp16_kernel<<<(n_vec + 255) / 256, 256>>>(x, n_vec);

    // 2) edge gather + abs-diff dot
    const int threads = 256;                      // 8 warps/block
    const int edges_per_block = (threads / 32) * 32;   // 256 edges
    const int blocks = (n_edges + edges_per_block - 1) / edges_per_block;
    edge_abs_dot_kernel<<<blocks, threads>>>(r_idx, c_idx, w, b, out,
                                             n_edges, n_nodes);
}